// round 12
// baseline (speedup 1.0000x reference)
#include <cuda_runtime.h>
#include <cuda_bf16.h>
#include <math_constants.h>
#include <cstdint>

// Problem constants (fixed by the dataset)
#define PP 16
#define CC 4
#define KK 8
#define NN 65536
#define DD 256
#define NROWS 64            // P*C
#define TILE_N 128
#define NB (NN / TILE_N)    // 512 blocks
#define INV_TEMP 20.0f

#define KC 64               // k-chunk
#define FB_STR 72           // bf16 stride of F chunk rows (64 + 8 pad)
#define XSTR 264            // bf16 stride of X tile rows

// smem layout (bytes)
#define FB0 0                              // F chunk buf0: 128 x FB_STR x 2 = 18432
#define FB1 (FB0 + 128 * FB_STR * 2)       // buf1: 18432
#define SX  (FB1 + 128 * FB_STR * 2)       // X tile: 64 x XSTR x 2 = 33792
#define SMEM_BYTES (SX + 64 * XSTR * 2)    // 70656 -> 2 CTAs/SM

// epilogue overlays
#define SRED_STRIDE 66                     // sRed[n][pc]: 128 x 66 floats (over FB0/FB1)

// Scratch
__device__ float          g_xb[NROWS * DD];
__device__ __nv_bfloat16  g_xh[NROWS * DD];
__device__ float4         g_part[NROWS * NB];   // packed (m, s, min, -) per (row, b)
__device__ unsigned g_cnt = 0;                  // gemm completion counter

// ---------------------------------------------------------------------------
// helpers
// ---------------------------------------------------------------------------
__device__ __forceinline__ uint32_t smem_u32(const void* p) {
    uint32_t a;
    asm("{ .reg .u64 t; cvta.to.shared.u64 t, %1; cvt.u32.u64 %0, t; }"
        : "=r"(a) : "l"(p));
    return a;
}

__device__ __forceinline__ void ldsm4(uint32_t* d, uint32_t a) {
    asm volatile("ldmatrix.sync.aligned.m8n8.x4.shared.b16 {%0,%1,%2,%3}, [%4];"
                 : "=r"(d[0]), "=r"(d[1]), "=r"(d[2]), "=r"(d[3]) : "r"(a));
}

__device__ __forceinline__ void mma16816(float* c, const uint32_t* a,
                                         const uint32_t b0, const uint32_t b1) {
    asm volatile(
        "mma.sync.aligned.m16n8k16.row.col.f32.bf16.bf16.f32 "
        "{%0,%1,%2,%3}, {%4,%5,%6,%7}, {%8,%9}, {%0,%1,%2,%3};"
        : "+f"(c[0]), "+f"(c[1]), "+f"(c[2]), "+f"(c[3])
        : "r"(a[0]), "r"(a[1]), "r"(a[2]), "r"(a[3]), "r"(b0), "r"(b1));
}

__device__ __forceinline__ unsigned cvt2(float lo, float hi) {
    unsigned r;
    asm("cvt.rn.bf16x2.f32 %0, %1, %2;" : "=r"(r) : "f"(hi), "f"(lo));
    return r;
}

// ---------------------------------------------------------------------------
// Kernel A: normalize, K-average, emit f32 + bf16. grid=64, block=512.
// (Proven R9 version; also resets the completion counter for this replay.)
// ---------------------------------------------------------------------------
__global__ void prep_kernel(const float* __restrict__ inputs) {
    const int pc = blockIdx.x;
    const int t  = threadIdx.x;        // 512
    const int k  = t >> 6;             // row within group (0..7)
    const int c4 = t & 63;             // float4 column (0..63)
    __shared__ float wsum[16];
    __shared__ float sxv[8][256];

    if (t == 0 && pc == 0) g_cnt = 0;  // reset last-block counter each replay

    float4 v = ((const float4*)inputs)[(size_t)(pc * KK + k) * 64 + c4];
    float sq = v.x * v.x + v.y * v.y + v.z * v.z + v.w * v.w;
    #pragma unroll
    for (int off = 16; off; off >>= 1)
        sq += __shfl_xor_sync(0xFFFFFFFFu, sq, off);
    if ((t & 31) == 0) wsum[t >> 5] = sq;
    __syncthreads();

    const float sc = rsqrtf(wsum[k * 2] + wsum[k * 2 + 1]) * (1.0f / (float)KK);
    *(float4*)&sxv[k][c4 * 4] = make_float4(v.x * sc, v.y * sc, v.z * sc, v.w * sc);
    __syncthreads();

    if (t < 256) {
        float a = 0.0f;
        #pragma unroll
        for (int kk = 0; kk < 8; kk++) a += sxv[kk][t];
        g_xb[pc * DD + t] = a;
        g_xh[pc * DD + t] = __float2bfloat16(a);
    }
}

// ---------------------------------------------------------------------------
// Kernel B: pipelined bf16 warp-MMA GEMM + fused partials; the LAST block to
// finish also combines all partials and writes the final loss.
// grid = NB (512), block = 256 (8 warps), 2 CTAs/SM.
// ---------------------------------------------------------------------------
__global__ void __launch_bounds__(256, 2)
gemm_reduce_kernel(const float* __restrict__ features,
                   float* __restrict__ out) {
    extern __shared__ char smem[];
    const uint32_t sb = smem_u32(smem);
    const int t = threadIdx.x;
    const int b = blockIdx.x;
    const int n0 = b * TILE_N;

    const float4* f4 = (const float4*)(features + (size_t)n0 * DD);
    float4 R[8];

    // ---- issue chunk-0 feature LDGs FIRST (in flight during X-tile phase) ----
    #pragma unroll
    for (int j = 0; j < 8; j++) {
        int idx = t + 256 * j;
        R[j] = f4[(idx >> 4) * 64 + (idx & 15)];
    }

    // ---- load x-bar bf16 tile (full K) while chunk-0 LDGs are in flight ----
    {
        const uint2* xh4 = (const uint2*)g_xh;
        #pragma unroll 4
        for (int i = t; i < NROWS * (DD / 4); i += 256) {
            int row  = i >> 6;
            int colq = i & 63;
            *(uint2*)(smem + SX + (uint32_t)(row * XSTR + colq * 4) * 2) = xh4[i];
        }
    }

    // ---- store chunk 0 ----
    #pragma unroll
    for (int j = 0; j < 8; j++) {
        int idx = t + 256 * j;
        int row = idx >> 4, q = idx & 15;
        *(uint2*)(smem + FB0 + (uint32_t)(row * FB_STR + q * 4) * 2) =
            make_uint2(cvt2(R[j].x, R[j].y), cvt2(R[j].z, R[j].w));
    }
    __syncthreads();

    const int lane  = t & 31;
    const int w     = t >> 5;
    const int nbase = (w & 3) * 32;
    const int pcbas = (w >> 2) * 32;

    const int aRow = nbase + (lane & 7) + ((lane >> 3) & 1) * 8;
    const int aCol = (lane >> 4) * 8;
    const int bRow = pcbas + (lane & 7) + (lane >> 4) * 8;
    const int bCol = ((lane >> 3) & 1) * 8;

    const uint32_t aOffL = (uint32_t)(aRow * FB_STR + aCol) * 2;
    const uint32_t bB = sb + SX + (uint32_t)(bRow * XSTR + bCol) * 2;

    float acc[2][4][4];
    #pragma unroll
    for (int i = 0; i < 2; i++)
        #pragma unroll
        for (int j = 0; j < 4; j++)
            #pragma unroll
            for (int q = 0; q < 4; q++) acc[i][j][q] = 0.0f;

    #pragma unroll
    for (int c = 0; c < 4; c++) {
        if (c < 3) {
            #pragma unroll
            for (int j = 0; j < 8; j++) {
                int idx = t + 256 * j;
                R[j] = f4[(idx >> 4) * 64 + (c + 1) * 16 + (idx & 15)];
            }
        }
        const uint32_t aBuf = sb + ((c & 1) ? FB1 : FB0) + aOffL;
        #pragma unroll
        for (int kst = 0; kst < 4; kst++) {
            uint32_t af[2][4], bfr[2][4];
            ldsm4(af[0], aBuf + kst * 32);
            ldsm4(af[1], aBuf + kst * 32 + 16 * FB_STR * 2);
            ldsm4(bfr[0], bB + (c * KC + kst * 16) * 2);
            ldsm4(bfr[1], bB + (c * KC + kst * 16) * 2 + 16 * XSTR * 2);
            #pragma unroll
            for (int mt = 0; mt < 2; mt++)
                #pragma unroll
                for (int ntp = 0; ntp < 2; ntp++) {
                    mma16816(acc[mt][ntp * 2 + 0], af[mt], bfr[ntp][0], bfr[ntp][1]);
                    mma16816(acc[mt][ntp * 2 + 1], af[mt], bfr[ntp][2], bfr[ntp][3]);
                }
        }
        if (c < 3) {
            // STS targets the buffer last read in chunk c-1 (already fenced by
            // that chunk's end barrier); MMAs of this chunk read the other buf.
            const int dst = (c & 1) ? FB0 : FB1;
            #pragma unroll
            for (int j = 0; j < 8; j++) {
                int idx = t + 256 * j;
                int row = idx >> 4, q = idx & 15;
                *(uint2*)(smem + dst + (uint32_t)(row * FB_STR + q * 4) * 2) =
                    make_uint2(cvt2(R[j].x, R[j].y), cvt2(R[j].z, R[j].w));
            }
            __syncthreads();
        }
    }
    __syncthreads();

    // ---- scatter accums to sRed[n][pc] (stride 66), overlays F buffers ----
    float* sRed = (float*)smem;
    {
        const int r0 = lane >> 2;
        const int c0 = (lane & 3) * 2;
        #pragma unroll
        for (int mt = 0; mt < 2; mt++)
            #pragma unroll
            for (int nt = 0; nt < 4; nt++) {
                const int n  = nbase + mt * 16 + r0;
                const int pc = pcbas + nt * 8 + c0;
                *(float2*)(sRed + n * SRED_STRIDE + pc) =
                    make_float2(acc[mt][nt][0], acc[mt][nt][1]);
                *(float2*)(sRed + (n + 8) * SRED_STRIDE + pc) =
                    make_float2(acc[mt][nt][2], acc[mt][nt][3]);
            }
    }
    __syncthreads();

    // ---- fused reduction: per pc column over 128 n-rows ----
    float* cm = (float*)(smem + SX);
    float* cs = cm + 256;
    float* cn = cm + 512;
    {
        const int col = t & 63;
        const int seg = t >> 6;
        const float* src = sRed + (seg * 32) * SRED_STRIDE + col;
        float m = -CUDART_INF_F, s = 0.0f, mn = CUDART_INF_F;
        #pragma unroll 8
        for (int j = 0; j < 32; j++) {
            float v = src[j * SRED_STRIDE] * INV_TEMP;
            float nm = fmaxf(m, v);
            s = s * __expf(m - nm) + __expf(v - nm);
            m = nm;
            mn = fminf(mn, v);
        }
        cm[seg * 64 + col] = m;
        cs[seg * 64 + col] = s;
        cn[seg * 64 + col] = mn;
    }
    __syncthreads();

    if (t < 64) {
        float m = -CUDART_INF_F, s = 0.0f, mn = CUDART_INF_F;
        #pragma unroll
        for (int seg = 0; seg < 4; seg++) {
            float pm = cm[seg * 64 + t], ps = cs[seg * 64 + t], pn = cn[seg * 64 + t];
            float nm = fmaxf(m, pm);
            s = s * __expf(m - nm) + ps * __expf(pm - nm);
            m = nm;
            mn = fminf(mn, pn);
        }
        g_part[t * NB + b] = make_float4(m, s, mn, 0.0f);
        __threadfence();                 // order partial writes before the signal
    }
    __syncthreads();

    // ---- last-block-done: the final block combines everything ----
    __shared__ unsigned isLast;
    if (t == 0) isLast = (atomicAdd(&g_cnt, 1u) == NB - 1u) ? 1u : 0u;
    __syncthreads();
    if (!isLast) return;
    __threadfence();                     // acquire all blocks' partials

    // reuse smem: result arrays
    float* rM   = (float*)smem;          // 64
    float* rS   = rM + 64;
    float* rMin = rM + 128;
    float* rOwn = rM + 192;

    // 8 warps x 8 rows: merge the 512 packed partials per row
    {
        const int row0 = w * 8;
        for (int j = 0; j < 8; j++) {
            const int row = row0 + j;
            const float4* src = g_part + row * NB;
            float m = -CUDART_INF_F, s = 0.0f, mn = CUDART_INF_F;
            #pragma unroll
            for (int q = 0; q < NB / 32; q++) {
                float4 pv = src[lane + q * 32];
                float nm = fmaxf(m, pv.x);
                s = s * __expf(m - nm) + pv.y * __expf(pv.x - nm);
                m = nm;
                mn = fminf(mn, pv.z);
            }
            #pragma unroll
            for (int off = 16; off; off >>= 1) {
                float mo  = __shfl_xor_sync(0xFFFFFFFFu, m,  off);
                float so  = __shfl_xor_sync(0xFFFFFFFFu, s,  off);
                float mno = __shfl_xor_sync(0xFFFFFFFFu, mn, off);
                float nm = fmaxf(m, mo);
                s = s * __expf(m - nm) + so * __expf(mo - nm);
                m = nm;
                mn = fminf(mn, mno);
            }
            // own-dot for this row
            const int p = row >> 2;
            float d = 0.0f;
            #pragma unroll
            for (int q = 0; q < DD / 32; q++)
                d = fmaf(g_xb[row * DD + lane + q * 32],
                         features[(size_t)p * DD + lane + q * 32], d);
            #pragma unroll
            for (int off = 16; off; off >>= 1)
                d += __shfl_xor_sync(0xFFFFFFFFu, d, off);
            if (lane == 0) {
                rM[row] = m; rS[row] = s; rMin[row] = mn;
                rOwn[row] = d * INV_TEMP;
            }
        }
    }
    __syncthreads();

    if (t < 32) {
        float loss = 0.0f;
        if (t < PP) {
            const int p2 = t;
            float M = -CUDART_INF_F;
            #pragma unroll
            for (int c = 0; c < CC; c++) M = fmaxf(M, rM[p2 * CC + c]);
            float S = 0.0f;
            #pragma unroll
            for (int c = 0; c < CC; c++)
                S += rS[p2 * CC + c] * expf(rM[p2 * CC + c] - M);
            #pragma unroll
            for (int c = 0; c < CC; c++)
                S -= expf(rMin[p2 * CC + c] - M);
            float pos = CUDART_INF_F;
            #pragma unroll
            for (int c = 0; c < CC; c++) pos = fminf(pos, rOwn[p2 * CC + c]);
            S += expf(pos - M);
            loss = (M + logf(S)) - pos;
        }
        #pragma unroll
        for (int off = 16; off; off >>= 1)
            loss += __shfl_xor_sync(0xFFFFFFFFu, loss, off);
        if (t == 0) out[0] = loss * (1.0f / (float)PP);
    }
}

// ---------------------------------------------------------------------------
extern "C" void kernel_launch(void* const* d_in, const int* in_sizes, int n_in,
                              void* d_out, int out_size) {
    const float* inputs   = (const float*)d_in[0];   // [512, 256] f32
    const float* features = (const float*)d_in[4];   // [65536, 256] f32
    float* out = (float*)d_out;

    cudaFuncSetAttribute(gemm_reduce_kernel,
                         cudaFuncAttributeMaxDynamicSharedMemorySize, SMEM_BYTES);

    prep_kernel<<<NROWS, 512>>>(inputs);
    gemm_reduce_kernel<<<NB, 256, SMEM_BYTES>>>(features, out);
}

// round 13
// speedup vs baseline: 1.2977x; 1.2977x over previous
#include <cuda_runtime.h>
#include <cuda_bf16.h>
#include <math_constants.h>
#include <cstdint>

// Problem constants (fixed by the dataset)
#define PP 16
#define CC 4
#define KK 8
#define NN 65536
#define DD 256
#define NROWS 64            // P*C
#define TILE_N 128
#define NB (NN / TILE_N)    // 512 blocks
#define INV_TEMP 20.0f

#define KC 64               // k-chunk
#define FB_STR 72           // bf16 stride of F chunk rows (64 + 8 pad)
#define XSTR 264            // bf16 stride of X tile rows

// smem layout (bytes)
#define FB0 0                              // F chunk buf0: 128 x FB_STR x 2 = 18432
#define FB1 (FB0 + 128 * FB_STR * 2)       // buf1: 18432
#define SX  (FB1 + 128 * FB_STR * 2)       // X tile: 64 x XSTR x 2 = 33792
#define SMEM_BYTES (SX + 64 * XSTR * 2)    // 70656 -> 2 CTAs/SM

// epilogue overlays
#define SRED_STRIDE 66                     // sRed[n][pc]: 128 x 66 floats (over FB0/FB1)

// Scratch
__device__ float          g_xb[NROWS * DD];
__device__ __nv_bfloat16  g_xh[NROWS * DD];
__device__ float4         g_part[NROWS * NB];   // packed (m, s, min, -) per (row, b)
__device__ float g_rM[NROWS], g_rS[NROWS], g_rMin[NROWS], g_own[NROWS];
__device__ unsigned g_cnt = 0;                  // combine completion counter

// ---------------------------------------------------------------------------
// helpers
// ---------------------------------------------------------------------------
__device__ __forceinline__ uint32_t smem_u32(const void* p) {
    uint32_t a;
    asm("{ .reg .u64 t; cvta.to.shared.u64 t, %1; cvt.u32.u64 %0, t; }"
        : "=r"(a) : "l"(p));
    return a;
}

__device__ __forceinline__ void ldsm4(uint32_t* d, uint32_t a) {
    asm volatile("ldmatrix.sync.aligned.m8n8.x4.shared.b16 {%0,%1,%2,%3}, [%4];"
                 : "=r"(d[0]), "=r"(d[1]), "=r"(d[2]), "=r"(d[3]) : "r"(a));
}

__device__ __forceinline__ void mma16816(float* c, const uint32_t* a,
                                         const uint32_t b0, const uint32_t b1) {
    asm volatile(
        "mma.sync.aligned.m16n8k16.row.col.f32.bf16.bf16.f32 "
        "{%0,%1,%2,%3}, {%4,%5,%6,%7}, {%8,%9}, {%0,%1,%2,%3};"
        : "+f"(c[0]), "+f"(c[1]), "+f"(c[2]), "+f"(c[3])
        : "r"(a[0]), "r"(a[1]), "r"(a[2]), "r"(a[3]), "r"(b0), "r"(b1));
}

__device__ __forceinline__ unsigned cvt2(float lo, float hi) {
    unsigned r;
    asm("cvt.rn.bf16x2.f32 %0, %1, %2;" : "=r"(r) : "f"(hi), "f"(lo));
    return r;
}

// ---------------------------------------------------------------------------
// Kernel A: normalize, K-average, emit f32 + bf16. grid=64, block=512.
// Triggers programmatic completion right after publishing x-bar.
// ---------------------------------------------------------------------------
__global__ void prep_kernel(const float* __restrict__ inputs) {
    const int pc = blockIdx.x;
    const int t  = threadIdx.x;        // 512
    const int k  = t >> 6;             // row within group (0..7)
    const int c4 = t & 63;             // float4 column (0..63)
    __shared__ float wsum[16];
    __shared__ float sxv[8][256];

    if (t == 0 && pc == 0) g_cnt = 0;  // reset combine counter each replay

    float4 v = ((const float4*)inputs)[(size_t)(pc * KK + k) * 64 + c4];
    float sq = v.x * v.x + v.y * v.y + v.z * v.z + v.w * v.w;
    #pragma unroll
    for (int off = 16; off; off >>= 1)
        sq += __shfl_xor_sync(0xFFFFFFFFu, sq, off);
    if ((t & 31) == 0) wsum[t >> 5] = sq;
    __syncthreads();

    const float sc = rsqrtf(wsum[k * 2] + wsum[k * 2 + 1]) * (1.0f / (float)KK);
    *(float4*)&sxv[k][c4 * 4] = make_float4(v.x * sc, v.y * sc, v.z * sc, v.w * sc);
    __syncthreads();

    if (t < 256) {
        float a = 0.0f;
        #pragma unroll
        for (int kk = 0; kk < 8; kk++) a += sxv[kk][t];
        g_xb[pc * DD + t] = a;
        g_xh[pc * DD + t] = __float2bfloat16(a);
    }
    cudaTriggerProgrammaticLaunchCompletion();
}

// ---------------------------------------------------------------------------
// Kernel B: pipelined bf16 warp-MMA GEMM + fused online-softmax/min partials.
// grid = NB (512), block = 256 (8 warps), 2 CTAs/SM. Launched with PDL:
// issues chunk-0 feature LDGs, then waits for prep before reading g_xh.
// ---------------------------------------------------------------------------
__global__ void __launch_bounds__(256, 2)
gemm_reduce_kernel(const float* __restrict__ features) {
    extern __shared__ char smem[];
    const uint32_t sb = smem_u32(smem);
    const int t = threadIdx.x;
    const int b = blockIdx.x;
    const int n0 = b * TILE_N;

    const float4* f4 = (const float4*)(features + (size_t)n0 * DD);
    float4 R[8];

    // ---- issue chunk-0 feature LDGs FIRST (overlap prep via PDL) ----
    #pragma unroll
    for (int j = 0; j < 8; j++) {
        int idx = t + 256 * j;
        R[j] = f4[(idx >> 4) * 64 + (idx & 15)];
    }

    // ---- wait for prep's x-bar publication ----
    cudaGridDependencySynchronize();

    // ---- load x-bar bf16 tile (full K) ----
    {
        const uint2* xh4 = (const uint2*)g_xh;
        #pragma unroll 4
        for (int i = t; i < NROWS * (DD / 4); i += 256) {
            int row  = i >> 6;
            int colq = i & 63;
            *(uint2*)(smem + SX + (uint32_t)(row * XSTR + colq * 4) * 2) = xh4[i];
        }
    }

    // ---- store chunk 0 ----
    #pragma unroll
    for (int j = 0; j < 8; j++) {
        int idx = t + 256 * j;
        int row = idx >> 4, q = idx & 15;
        *(uint2*)(smem + FB0 + (uint32_t)(row * FB_STR + q * 4) * 2) =
            make_uint2(cvt2(R[j].x, R[j].y), cvt2(R[j].z, R[j].w));
    }
    __syncthreads();

    const int lane  = t & 31;
    const int w     = t >> 5;
    const int nbase = (w & 3) * 32;
    const int pcbas = (w >> 2) * 32;

    const int aRow = nbase + (lane & 7) + ((lane >> 3) & 1) * 8;
    const int aCol = (lane >> 4) * 8;
    const int bRow = pcbas + (lane & 7) + (lane >> 4) * 8;
    const int bCol = ((lane >> 3) & 1) * 8;

    const uint32_t aOffL = (uint32_t)(aRow * FB_STR + aCol) * 2;
    const uint32_t bB = sb + SX + (uint32_t)(bRow * XSTR + bCol) * 2;

    float acc[2][4][4];
    #pragma unroll
    for (int i = 0; i < 2; i++)
        #pragma unroll
        for (int j = 0; j < 4; j++)
            #pragma unroll
            for (int q = 0; q < 4; q++) acc[i][j][q] = 0.0f;

    #pragma unroll
    for (int c = 0; c < 4; c++) {
        if (c < 3) {
            #pragma unroll
            for (int j = 0; j < 8; j++) {
                int idx = t + 256 * j;
                R[j] = f4[(idx >> 4) * 64 + (c + 1) * 16 + (idx & 15)];
            }
        }
        const uint32_t aBuf = sb + ((c & 1) ? FB1 : FB0) + aOffL;
        #pragma unroll
        for (int kst = 0; kst < 4; kst++) {
            uint32_t af[2][4], bfr[2][4];
            ldsm4(af[0], aBuf + kst * 32);
            ldsm4(af[1], aBuf + kst * 32 + 16 * FB_STR * 2);
            ldsm4(bfr[0], bB + (c * KC + kst * 16) * 2);
            ldsm4(bfr[1], bB + (c * KC + kst * 16) * 2 + 16 * XSTR * 2);
            #pragma unroll
            for (int mt = 0; mt < 2; mt++)
                #pragma unroll
                for (int ntp = 0; ntp < 2; ntp++) {
                    mma16816(acc[mt][ntp * 2 + 0], af[mt], bfr[ntp][0], bfr[ntp][1]);
                    mma16816(acc[mt][ntp * 2 + 1], af[mt], bfr[ntp][2], bfr[ntp][3]);
                }
        }
        if (c < 3) {
            // STS targets the buffer last read in chunk c-1 (already fenced by
            // that chunk's end barrier); MMAs of this chunk read the other buf.
            const int dst = (c & 1) ? FB0 : FB1;
            #pragma unroll
            for (int j = 0; j < 8; j++) {
                int idx = t + 256 * j;
                int row = idx >> 4, q = idx & 15;
                *(uint2*)(smem + dst + (uint32_t)(row * FB_STR + q * 4) * 2) =
                    make_uint2(cvt2(R[j].x, R[j].y), cvt2(R[j].z, R[j].w));
            }
            __syncthreads();
        }
    }
    __syncthreads();

    // ---- scatter accums to sRed[n][pc] (stride 66), overlays F buffers ----
    float* sRed = (float*)smem;
    {
        const int r0 = lane >> 2;
        const int c0 = (lane & 3) * 2;
        #pragma unroll
        for (int mt = 0; mt < 2; mt++)
            #pragma unroll
            for (int nt = 0; nt < 4; nt++) {
                const int n  = nbase + mt * 16 + r0;
                const int pc = pcbas + nt * 8 + c0;
                *(float2*)(sRed + n * SRED_STRIDE + pc) =
                    make_float2(acc[mt][nt][0], acc[mt][nt][1]);
                *(float2*)(sRed + (n + 8) * SRED_STRIDE + pc) =
                    make_float2(acc[mt][nt][2], acc[mt][nt][3]);
            }
    }
    __syncthreads();

    // ---- fused reduction: per pc column over 128 n-rows ----
    float* cm = (float*)(smem + SX);
    float* cs = cm + 256;
    float* cn = cm + 512;
    {
        const int col = t & 63;
        const int seg = t >> 6;
        const float* src = sRed + (seg * 32) * SRED_STRIDE + col;
        float m = -CUDART_INF_F, s = 0.0f, mn = CUDART_INF_F;
        #pragma unroll 8
        for (int j = 0; j < 32; j++) {
            float v = src[j * SRED_STRIDE] * INV_TEMP;
            float nm = fmaxf(m, v);
            s = s * __expf(m - nm) + __expf(v - nm);
            m = nm;
            mn = fminf(mn, v);
        }
        cm[seg * 64 + col] = m;
        cs[seg * 64 + col] = s;
        cn[seg * 64 + col] = mn;
    }
    __syncthreads();

    if (t < 64) {
        float m = -CUDART_INF_F, s = 0.0f, mn = CUDART_INF_F;
        #pragma unroll
        for (int seg = 0; seg < 4; seg++) {
            float pm = cm[seg * 64 + t], ps = cs[seg * 64 + t], pn = cn[seg * 64 + t];
            float nm = fmaxf(m, pm);
            s = s * __expf(m - nm) + ps * __expf(pm - nm);
            m = nm;
            mn = fminf(mn, pn);
        }
        g_part[t * NB + b] = make_float4(m, s, mn, 0.0f);
    }
}

// ---------------------------------------------------------------------------
// Kernel C: per-row combine of the 512 packed partials + own-dot; LAST block
// also assembles the scalar loss. grid=64, block=128. PDL-dependent on gemm.
// ---------------------------------------------------------------------------
__global__ void combine_kernel(const float* __restrict__ features,
                               float* __restrict__ out) {
    const int row = blockIdx.x;
    const int t = threadIdx.x;       // 128
    const int w = t >> 5, l = t & 31;
    __shared__ float pm[4], ps[4], pn[4], pd[4];
    __shared__ int isLast;

    // own-dot partial first: depends only on prep outputs (long complete)
    const int p = row >> 2;
    float d = g_xb[row * DD + t] * features[(size_t)p * DD + t]
            + g_xb[row * DD + t + 128] * features[(size_t)p * DD + t + 128];
    #pragma unroll
    for (int off = 16; off; off >>= 1)
        d += __shfl_xor_sync(0xFFFFFFFFu, d, off);

    // wait for gemm before touching its partials
    cudaGridDependencySynchronize();

    float m = -CUDART_INF_F, s = 0.0f, mn = CUDART_INF_F;
    #pragma unroll
    for (int j = 0; j < 4; j++) {
        float4 pv = g_part[row * NB + t + 128 * j];
        float nm = fmaxf(m, pv.x);
        s = s * __expf(m - nm) + pv.y * __expf(pv.x - nm);
        m = nm;
        mn = fminf(mn, pv.z);
    }
    #pragma unroll
    for (int off = 16; off; off >>= 1) {
        float mo  = __shfl_xor_sync(0xFFFFFFFFu, m,  off);
        float so  = __shfl_xor_sync(0xFFFFFFFFu, s,  off);
        float mno = __shfl_xor_sync(0xFFFFFFFFu, mn, off);
        float nm = fmaxf(m, mo);
        s = s * __expf(m - nm) + so * __expf(mo - nm);
        m = nm;
        mn = fminf(mn, mno);
    }

    if (l == 0) { pm[w] = m; ps[w] = s; pn[w] = mn; pd[w] = d; }
    __syncthreads();

    if (t == 0) {
        float M = pm[0], S = ps[0], MN = pn[0], D = pd[0];
        #pragma unroll
        for (int i = 1; i < 4; i++) {
            float nm = fmaxf(M, pm[i]);
            S = S * expf(M - nm) + ps[i] * expf(pm[i] - nm);
            M = nm;
            MN = fminf(MN, pn[i]);
            D += pd[i];
        }
        g_rM[row] = M; g_rS[row] = S; g_rMin[row] = MN;
        g_own[row] = D * INV_TEMP;
        __threadfence();
        unsigned r = atomicAdd(&g_cnt, 1u);
        if (r == NROWS - 1) __threadfence();   // acquire all rows' results
        isLast = (r == NROWS - 1);
    }
    __syncthreads();

    if (isLast && t < 32) {
        float loss = 0.0f;
        if (t < PP) {
            const int p2 = t;
            float M = -CUDART_INF_F;
            #pragma unroll
            for (int c = 0; c < CC; c++) M = fmaxf(M, g_rM[p2 * CC + c]);
            float S = 0.0f;
            #pragma unroll
            for (int c = 0; c < CC; c++)
                S += g_rS[p2 * CC + c] * expf(g_rM[p2 * CC + c] - M);
            #pragma unroll
            for (int c = 0; c < CC; c++)
                S -= expf(g_rMin[p2 * CC + c] - M);
            float pos = CUDART_INF_F;
            #pragma unroll
            for (int c = 0; c < CC; c++) pos = fminf(pos, g_own[p2 * CC + c]);
            S += expf(pos - M);
            loss = (M + logf(S)) - pos;
        }
        #pragma unroll
        for (int off = 16; off; off >>= 1)
            loss += __shfl_xor_sync(0xFFFFFFFFu, loss, off);
        if (t == 0) out[0] = loss * (1.0f / (float)PP);
    }
}

// ---------------------------------------------------------------------------
extern "C" void kernel_launch(void* const* d_in, const int* in_sizes, int n_in,
                              void* d_out, int out_size) {
    const float* inputs   = (const float*)d_in[0];   // [512, 256] f32
    const float* features = (const float*)d_in[4];   // [65536, 256] f32
    float* out = (float*)d_out;

    cudaFuncSetAttribute(gemm_reduce_kernel,
                         cudaFuncAttributeMaxDynamicSharedMemorySize, SMEM_BYTES);

    prep_kernel<<<NROWS, 512>>>(inputs);

    // gemm: PDL-dependent on prep
    {
        cudaLaunchAttribute attr[1];
        attr[0].id = cudaLaunchAttributeProgrammaticStreamSerialization;
        attr[0].val.programmaticStreamSerializationAllowed = 1;
        cudaLaunchConfig_t cfg = {};
        cfg.gridDim = dim3(NB, 1, 1);
        cfg.blockDim = dim3(256, 1, 1);
        cfg.dynamicSmemBytes = SMEM_BYTES;
        cfg.stream = 0;
        cfg.attrs = attr;
        cfg.numAttrs = 1;
        cudaLaunchKernelEx(&cfg, gemm_reduce_kernel, features);
    }

    // combine: PDL-dependent on gemm
    {
        cudaLaunchAttribute attr[1];
        attr[0].id = cudaLaunchAttributeProgrammaticStreamSerialization;
        attr[0].val.programmaticStreamSerializationAllowed = 1;
        cudaLaunchConfig_t cfg = {};
        cfg.gridDim = dim3(NROWS, 1, 1);
        cfg.blockDim = dim3(128, 1, 1);
        cfg.dynamicSmemBytes = 0;
        cfg.stream = 0;
        cfg.attrs = attr;
        cfg.numAttrs = 1;
        cudaLaunchKernelEx(&cfg, combine_kernel, features, out);
    }
}

// round 14
// speedup vs baseline: 1.4076x; 1.0846x over previous
#include <cuda_runtime.h>
#include <cuda_bf16.h>
#include <math_constants.h>
#include <cstdint>

// Problem constants (fixed by the dataset)
#define PP 16
#define CC 4
#define KK 8
#define NN 65536
#define DD 256
#define NROWS 64            // P*C
#define TILE_N 128
#define NB (NN / TILE_N)    // 512 tiles
#define GRID_B (NB / 2)     // 256 blocks, 2 tiles each (single wave)
#define INV_TEMP 20.0f

#define KC 64               // k-chunk
#define FB_STR 72           // bf16 stride of F chunk rows (64 + 8 pad)
#define XSTR 264            // bf16 stride of X tile rows

// smem layout (bytes)
#define FB0 0                              // F chunk buf0: 128 x FB_STR x 2 = 18432
#define FB1 (FB0 + 128 * FB_STR * 2)       // buf1: 18432
#define SX  (FB1 + 128 * FB_STR * 2)       // X tile: 64 x XSTR x 2 = 33792
#define SMEM_BYTES (SX + 64 * XSTR * 2)    // 70656 -> 2 CTAs/SM

// epilogue overlays (inside FB region; X tile at SX stays intact across tiles)
#define SRED_STRIDE 66                     // sRed[n][pc]: 128 x 66 floats = 33792 B
#define CS_OFF 33792                       // cs/cn: 512 floats = 2048 B (fits < 36864)

// Scratch
__device__ float          g_xb[NROWS * DD];
__device__ __nv_bfloat16  g_xh[NROWS * DD];
__device__ float2         g_part[NROWS * NB];   // packed (sum, min) per (row, tile)
__device__ float g_rS[NROWS], g_rMin[NROWS], g_own[NROWS];
__device__ unsigned g_cnt = 0;                  // combine completion counter

// ---------------------------------------------------------------------------
// helpers
// ---------------------------------------------------------------------------
__device__ __forceinline__ uint32_t smem_u32(const void* p) {
    uint32_t a;
    asm("{ .reg .u64 t; cvta.to.shared.u64 t, %1; cvt.u32.u64 %0, t; }"
        : "=r"(a) : "l"(p));
    return a;
}

__device__ __forceinline__ void ldsm4(uint32_t* d, uint32_t a) {
    asm volatile("ldmatrix.sync.aligned.m8n8.x4.shared.b16 {%0,%1,%2,%3}, [%4];"
                 : "=r"(d[0]), "=r"(d[1]), "=r"(d[2]), "=r"(d[3]) : "r"(a));
}

__device__ __forceinline__ void mma16816(float* c, const uint32_t* a,
                                         const uint32_t b0, const uint32_t b1) {
    asm volatile(
        "mma.sync.aligned.m16n8k16.row.col.f32.bf16.bf16.f32 "
        "{%0,%1,%2,%3}, {%4,%5,%6,%7}, {%8,%9}, {%0,%1,%2,%3};"
        : "+f"(c[0]), "+f"(c[1]), "+f"(c[2]), "+f"(c[3])
        : "r"(a[0]), "r"(a[1]), "r"(a[2]), "r"(a[3]), "r"(b0), "r"(b1));
}

__device__ __forceinline__ unsigned cvt2(float lo, float hi) {
    unsigned r;
    asm("cvt.rn.bf16x2.f32 %0, %1, %2;" : "=r"(r) : "f"(hi), "f"(lo));
    return r;
}

// ---------------------------------------------------------------------------
// Kernel A: normalize, K-average, emit f32 + bf16. grid=64, block=512.
// Triggers programmatic completion right after publishing x-bar.
// ---------------------------------------------------------------------------
__global__ void prep_kernel(const float* __restrict__ inputs) {
    const int pc = blockIdx.x;
    const int t  = threadIdx.x;        // 512
    const int k  = t >> 6;             // row within group (0..7)
    const int c4 = t & 63;             // float4 column (0..63)
    __shared__ float wsum[16];
    __shared__ float sxv[8][256];

    if (t == 0 && pc == 0) g_cnt = 0;  // reset combine counter each replay

    float4 v = ((const float4*)inputs)[(size_t)(pc * KK + k) * 64 + c4];
    float sq = v.x * v.x + v.y * v.y + v.z * v.z + v.w * v.w;
    #pragma unroll
    for (int off = 16; off; off >>= 1)
        sq += __shfl_xor_sync(0xFFFFFFFFu, sq, off);
    if ((t & 31) == 0) wsum[t >> 5] = sq;
    __syncthreads();

    const float sc = rsqrtf(wsum[k * 2] + wsum[k * 2 + 1]) * (1.0f / (float)KK);
    *(float4*)&sxv[k][c4 * 4] = make_float4(v.x * sc, v.y * sc, v.z * sc, v.w * sc);
    __syncthreads();

    if (t < 256) {
        float a = 0.0f;
        #pragma unroll
        for (int kk = 0; kk < 8; kk++) a += sxv[kk][t];
        g_xb[pc * DD + t] = a;
        g_xh[pc * DD + t] = __float2bfloat16(a);
    }
    cudaTriggerProgrammaticLaunchCompletion();
}

// ---------------------------------------------------------------------------
// Kernel B: persistent 2-tile pipelined bf16 warp-MMA GEMM + fused
// sum-exp/min partials (no max shift: v in [-20,20] cannot overflow f32).
// grid = 256 (single wave), block = 256 (8 warps), 2 CTAs/SM. PDL on prep.
// ---------------------------------------------------------------------------
__global__ void __launch_bounds__(256, 2)
gemm_reduce_kernel(const float* __restrict__ features) {
    extern __shared__ char smem[];
    const uint32_t sb = smem_u32(smem);
    const int t = threadIdx.x;
    const int bid = blockIdx.x;

    const float4* fb = (const float4*)features;
    float4 R[8];

    // ---- prefetch tile-0 chunk-0 (overlaps prep via PDL) ----
    {
        const float4* f40 = fb + (size_t)bid * TILE_N * 64;
        #pragma unroll
        for (int j = 0; j < 8; j++) {
            int idx = t + 256 * j;
            R[j] = f40[(idx >> 4) * 64 + (idx & 15)];
        }
    }

    cudaGridDependencySynchronize();   // wait for prep's x-bar

    // ---- load x-bar bf16 tile (full K), persists across both tiles ----
    {
        const uint2* xh4 = (const uint2*)g_xh;
        #pragma unroll 4
        for (int i = t; i < NROWS * (DD / 4); i += 256) {
            int row  = i >> 6;
            int colq = i & 63;
            *(uint2*)(smem + SX + (uint32_t)(row * XSTR + colq * 4) * 2) = xh4[i];
        }
    }

    const int lane  = t & 31;
    const int w     = t >> 5;
    const int nbase = (w & 3) * 32;
    const int pcbas = (w >> 2) * 32;

    const int aRow = nbase + (lane & 7) + ((lane >> 3) & 1) * 8;
    const int aCol = (lane >> 4) * 8;
    const int bRow = pcbas + (lane & 7) + (lane >> 4) * 8;
    const int bCol = ((lane >> 3) & 1) * 8;

    const uint32_t aOffL = (uint32_t)(aRow * FB_STR + aCol) * 2;
    const uint32_t bB = sb + SX + (uint32_t)(bRow * XSTR + bCol) * 2;

    #pragma unroll 1
    for (int tile = 0; tile < 2; tile++) {
        const float4* f4 = fb + (size_t)(bid + tile * GRID_B) * TILE_N * 64;

        // ---- store chunk 0 (R holds it: prologue / prev-tile prefetch) ----
        #pragma unroll
        for (int j = 0; j < 8; j++) {
            int idx = t + 256 * j;
            int row = idx >> 4, q = idx & 15;
            *(uint2*)(smem + FB0 + (uint32_t)(row * FB_STR + q * 4) * 2) =
                make_uint2(cvt2(R[j].x, R[j].y), cvt2(R[j].z, R[j].w));
        }
        __syncthreads();

        float acc[2][4][4];
        #pragma unroll
        for (int i = 0; i < 2; i++)
            #pragma unroll
            for (int j = 0; j < 4; j++)
                #pragma unroll
                for (int q = 0; q < 4; q++) acc[i][j][q] = 0.0f;

        #pragma unroll
        for (int c = 0; c < 4; c++) {
            if (c < 3) {
                #pragma unroll
                for (int j = 0; j < 8; j++) {
                    int idx = t + 256 * j;
                    R[j] = f4[(idx >> 4) * 64 + (c + 1) * 16 + (idx & 15)];
                }
            } else if (tile == 0) {
                // prefetch next tile's chunk 0 during last MMA chunk
                const float4* f4n = fb + (size_t)(bid + GRID_B) * TILE_N * 64;
                #pragma unroll
                for (int j = 0; j < 8; j++) {
                    int idx = t + 256 * j;
                    R[j] = f4n[(idx >> 4) * 64 + (idx & 15)];
                }
            }
            const uint32_t aBuf = sb + ((c & 1) ? FB1 : FB0) + aOffL;
            #pragma unroll
            for (int kst = 0; kst < 4; kst++) {
                uint32_t af[2][4], bfr[2][4];
                ldsm4(af[0], aBuf + kst * 32);
                ldsm4(af[1], aBuf + kst * 32 + 16 * FB_STR * 2);
                ldsm4(bfr[0], bB + (c * KC + kst * 16) * 2);
                ldsm4(bfr[1], bB + (c * KC + kst * 16) * 2 + 16 * XSTR * 2);
                #pragma unroll
                for (int mt = 0; mt < 2; mt++)
                    #pragma unroll
                    for (int ntp = 0; ntp < 2; ntp++) {
                        mma16816(acc[mt][ntp * 2 + 0], af[mt], bfr[ntp][0], bfr[ntp][1]);
                        mma16816(acc[mt][ntp * 2 + 1], af[mt], bfr[ntp][2], bfr[ntp][3]);
                    }
            }
            if (c < 3) {
                const int dst = (c & 1) ? FB0 : FB1;
                #pragma unroll
                for (int j = 0; j < 8; j++) {
                    int idx = t + 256 * j;
                    int row = idx >> 4, q = idx & 15;
                    *(uint2*)(smem + dst + (uint32_t)(row * FB_STR + q * 4) * 2) =
                        make_uint2(cvt2(R[j].x, R[j].y), cvt2(R[j].z, R[j].w));
                }
                __syncthreads();
            }
        }
        __syncthreads();

        // ---- scatter accums to sRed[n][pc] (overlays FB region only) ----
        float* sRed = (float*)smem;
        {
            const int r0 = lane >> 2;
            const int c0 = (lane & 3) * 2;
            #pragma unroll
            for (int mt = 0; mt < 2; mt++)
                #pragma unroll
                for (int nt = 0; nt < 4; nt++) {
                    const int n  = nbase + mt * 16 + r0;
                    const int pc = pcbas + nt * 8 + c0;
                    *(float2*)(sRed + n * SRED_STRIDE + pc) =
                        make_float2(acc[mt][nt][0], acc[mt][nt][1]);
                    *(float2*)(sRed + (n + 8) * SRED_STRIDE + pc) =
                        make_float2(acc[mt][nt][2], acc[mt][nt][3]);
                }
        }
        __syncthreads();

        // ---- fused reduction: per pc column -> (sum exp, min); no max shift
        float* cs = (float*)(smem + CS_OFF);
        float* cn = cs + 256;
        {
            const int col = t & 63;
            const int seg = t >> 6;
            const float* src = sRed + (seg * 32) * SRED_STRIDE + col;
            float s = 0.0f, mn = CUDART_INF_F;
            #pragma unroll 8
            for (int j = 0; j < 32; j++) {
                float v = src[j * SRED_STRIDE] * INV_TEMP;
                s += __expf(v);
                mn = fminf(mn, v);
            }
            cs[seg * 64 + col] = s;
            cn[seg * 64 + col] = mn;
        }
        __syncthreads();

        if (t < 64) {
            float s = 0.0f, mn = CUDART_INF_F;
            #pragma unroll
            for (int seg = 0; seg < 4; seg++) {
                s += cs[seg * 64 + t];
                mn = fminf(mn, cn[seg * 64 + t]);
            }
            g_part[t * NB + (bid + tile * GRID_B)] = make_float2(s, mn);
        }
        // no barrier needed: next tile's chunk-0 STS hits FB0 only, disjoint
        // from cs/cn (FB1 region); sRed readers already fenced above.
    }
}

// ---------------------------------------------------------------------------
// Kernel C: per-row combine of the 512 packed partials + own-dot; LAST block
// also assembles the scalar loss. grid=64, block=128. PDL-dependent on gemm.
// ---------------------------------------------------------------------------
__global__ void combine_kernel(const float* __restrict__ features,
                               float* __restrict__ out) {
    const int row = blockIdx.x;
    const int t = threadIdx.x;       // 128
    const int w = t >> 5, l = t & 31;
    __shared__ float ps[4], pn[4], pd[4];
    __shared__ int isLast;

    // own-dot partial first: depends only on prep outputs (long complete)
    const int p = row >> 2;
    float d = g_xb[row * DD + t] * features[(size_t)p * DD + t]
            + g_xb[row * DD + t + 128] * features[(size_t)p * DD + t + 128];
    #pragma unroll
    for (int off = 16; off; off >>= 1)
        d += __shfl_xor_sync(0xFFFFFFFFu, d, off);

    // wait for gemm before touching its partials
    cudaGridDependencySynchronize();

    float s = 0.0f, mn = CUDART_INF_F;
    #pragma unroll
    for (int j = 0; j < 4; j++) {
        float2 pv = g_part[row * NB + t + 128 * j];
        s += pv.x;
        mn = fminf(mn, pv.y);
    }
    #pragma unroll
    for (int off = 16; off; off >>= 1) {
        s  += __shfl_xor_sync(0xFFFFFFFFu, s,  off);
        mn  = fminf(mn, __shfl_xor_sync(0xFFFFFFFFu, mn, off));
    }

    if (l == 0) { ps[w] = s; pn[w] = mn; pd[w] = d; }
    __syncthreads();

    if (t == 0) {
        float S = ps[0], MN = pn[0], D = pd[0];
        #pragma unroll
        for (int i = 1; i < 4; i++) {
            S += ps[i];
            MN = fminf(MN, pn[i]);
            D += pd[i];
        }
        g_rS[row] = S; g_rMin[row] = MN;
        g_own[row] = D * INV_TEMP;
        __threadfence();
        unsigned r = atomicAdd(&g_cnt, 1u);
        if (r == NROWS - 1) __threadfence();   // acquire all rows' results
        isLast = (r == NROWS - 1);
    }
    __syncthreads();

    if (isLast && t < 32) {
        float loss = 0.0f;
        if (t < PP) {
            const int p2 = t;
            float S = 0.0f;
            #pragma unroll
            for (int c = 0; c < CC; c++) S += g_rS[p2 * CC + c];
            #pragma unroll
            for (int c = 0; c < CC; c++) S -= expf(g_rMin[p2 * CC + c]);
            float pos = CUDART_INF_F;
            #pragma unroll
            for (int c = 0; c < CC; c++) pos = fminf(pos, g_own[p2 * CC + c]);
            S += expf(pos);
            loss = logf(S) - pos;
        }
        #pragma unroll
        for (int off = 16; off; off >>= 1)
            loss += __shfl_xor_sync(0xFFFFFFFFu, loss, off);
        if (t == 0) out[0] = loss * (1.0f / (float)PP);
    }
}

// ---------------------------------------------------------------------------
extern "C" void kernel_launch(void* const* d_in, const int* in_sizes, int n_in,
                              void* d_out, int out_size) {
    const float* inputs   = (const float*)d_in[0];   // [512, 256] f32
    const float* features = (const float*)d_in[4];   // [65536, 256] f32
    float* out = (float*)d_out;

    cudaFuncSetAttribute(gemm_reduce_kernel,
                         cudaFuncAttributeMaxDynamicSharedMemorySize, SMEM_BYTES);

    prep_kernel<<<NROWS, 512>>>(inputs);

    // gemm: PDL-dependent on prep
    {
        cudaLaunchAttribute attr[1];
        attr[0].id = cudaLaunchAttributeProgrammaticStreamSerialization;
        attr[0].val.programmaticStreamSerializationAllowed = 1;
        cudaLaunchConfig_t cfg = {};
        cfg.gridDim = dim3(GRID_B, 1, 1);
        cfg.blockDim = dim3(256, 1, 1);
        cfg.dynamicSmemBytes = SMEM_BYTES;
        cfg.stream = 0;
        cfg.attrs = attr;
        cfg.numAttrs = 1;
        cudaLaunchKernelEx(&cfg, gemm_reduce_kernel, features);
    }

    // combine: PDL-dependent on gemm
    {
        cudaLaunchAttribute attr[1];
        attr[0].id = cudaLaunchAttributeProgrammaticStreamSerialization;
        attr[0].val.programmaticStreamSerializationAllowed = 1;
        cudaLaunchConfig_t cfg = {};
        cfg.gridDim = dim3(NROWS, 1, 1);
        cfg.blockDim = dim3(128, 1, 1);
        cfg.dynamicSmemBytes = 0;
        cfg.stream = 0;
        cfg.attrs = attr;
        cfg.numAttrs = 1;
        cudaLaunchKernelEx(&cfg, combine_kernel, features, out);
    }
}

// round 15
// speedup vs baseline: 1.5333x; 1.0894x over previous
#include <cuda_runtime.h>
#include <cuda_bf16.h>
#include <math_constants.h>
#include <cstdint>

// Problem constants (fixed by the dataset)
#define PP 16
#define CC 4
#define KK 8
#define NN 65536
#define DD 256
#define NROWS 64            // P*C
#define TILE_N 128
#define NB (NN / TILE_N)    // 512 tiles
#define GRID_B (NB / 2)     // 256 blocks, 2 tiles each (single wave)
#define INV_TEMP 20.0f

#define KC 64               // k-chunk
#define FB_STR 72           // bf16 stride of F chunk rows (64 + 8 pad)
#define XSTR 264            // bf16 stride of X tile rows

// smem layout (bytes)
#define FB0 0                              // F chunk buf0: 128 x FB_STR x 2 = 18432
#define FB1 (FB0 + 128 * FB_STR * 2)       // buf1: 18432
#define SX  (FB1 + 128 * FB_STR * 2)       // X tile: 64 x XSTR x 2 = 33792
#define SMEM_BYTES (SX + 64 * XSTR * 2)    // 70656 -> 2 CTAs/SM

// epilogue scratch: cs/cn [4 n-groups][64 cols] x 2 = 2048 B, inside FB1 region
#define CS_OFF 20480

// Scratch
__device__ float          g_xb[NROWS * DD];
__device__ __nv_bfloat16  g_xh[NROWS * DD];
__device__ float2         g_part[NROWS * NB];   // packed (sum, min) per (row, tile)
__device__ float g_rS[NROWS], g_rMin[NROWS], g_own[NROWS];
__device__ unsigned g_cnt = 0;                  // combine completion counter

// ---------------------------------------------------------------------------
// helpers
// ---------------------------------------------------------------------------
__device__ __forceinline__ uint32_t smem_u32(const void* p) {
    uint32_t a;
    asm("{ .reg .u64 t; cvta.to.shared.u64 t, %1; cvt.u32.u64 %0, t; }"
        : "=r"(a) : "l"(p));
    return a;
}

__device__ __forceinline__ void ldsm4(uint32_t* d, uint32_t a) {
    asm volatile("ldmatrix.sync.aligned.m8n8.x4.shared.b16 {%0,%1,%2,%3}, [%4];"
                 : "=r"(d[0]), "=r"(d[1]), "=r"(d[2]), "=r"(d[3]) : "r"(a));
}

__device__ __forceinline__ void mma16816(float* c, const uint32_t* a,
                                         const uint32_t b0, const uint32_t b1) {
    asm volatile(
        "mma.sync.aligned.m16n8k16.row.col.f32.bf16.bf16.f32 "
        "{%0,%1,%2,%3}, {%4,%5,%6,%7}, {%8,%9}, {%0,%1,%2,%3};"
        : "+f"(c[0]), "+f"(c[1]), "+f"(c[2]), "+f"(c[3])
        : "r"(a[0]), "r"(a[1]), "r"(a[2]), "r"(a[3]), "r"(b0), "r"(b1));
}

__device__ __forceinline__ unsigned cvt2(float lo, float hi) {
    unsigned r;
    asm("cvt.rn.bf16x2.f32 %0, %1, %2;" : "=r"(r) : "f"(hi), "f"(lo));
    return r;
}

// ---------------------------------------------------------------------------
// Kernel A: normalize, K-average, emit f32 + bf16. grid=64, block=512.
// ---------------------------------------------------------------------------
__global__ void prep_kernel(const float* __restrict__ inputs) {
    const int pc = blockIdx.x;
    const int t  = threadIdx.x;        // 512
    const int k  = t >> 6;             // row within group (0..7)
    const int c4 = t & 63;             // float4 column (0..63)
    __shared__ float wsum[16];
    __shared__ float sxv[8][256];

    if (t == 0 && pc == 0) g_cnt = 0;  // reset combine counter each replay

    float4 v = ((const float4*)inputs)[(size_t)(pc * KK + k) * 64 + c4];
    float sq = v.x * v.x + v.y * v.y + v.z * v.z + v.w * v.w;
    #pragma unroll
    for (int off = 16; off; off >>= 1)
        sq += __shfl_xor_sync(0xFFFFFFFFu, sq, off);
    if ((t & 31) == 0) wsum[t >> 5] = sq;
    __syncthreads();

    const float sc = rsqrtf(wsum[k * 2] + wsum[k * 2 + 1]) * (1.0f / (float)KK);
    *(float4*)&sxv[k][c4 * 4] = make_float4(v.x * sc, v.y * sc, v.z * sc, v.w * sc);
    __syncthreads();

    if (t < 256) {
        float a = 0.0f;
        #pragma unroll
        for (int kk = 0; kk < 8; kk++) a += sxv[kk][t];
        g_xb[pc * DD + t] = a;
        g_xh[pc * DD + t] = __float2bfloat16(a);
    }
    cudaTriggerProgrammaticLaunchCompletion();
}

// ---------------------------------------------------------------------------
// Kernel B: persistent 2-tile pipelined bf16 warp-MMA GEMM with all-register
// epilogue (exp-sum/min via shfl over the MMA fragment layout).
// grid = 256 (single wave), block = 256 (8 warps), 2 CTAs/SM. PDL on prep.
// ---------------------------------------------------------------------------
__global__ void __launch_bounds__(256, 2)
gemm_reduce_kernel(const float* __restrict__ features) {
    extern __shared__ char smem[];
    const uint32_t sb = smem_u32(smem);
    const int t = threadIdx.x;
    const int bid = blockIdx.x;

    const float4* fb = (const float4*)features;
    float4 R[8];

    // ---- prefetch tile-0 chunk-0 (overlaps prep via PDL) ----
    {
        const float4* f40 = fb + (size_t)bid * TILE_N * 64;
        #pragma unroll
        for (int j = 0; j < 8; j++) {
            int idx = t + 256 * j;
            R[j] = f40[(idx >> 4) * 64 + (idx & 15)];
        }
    }

    cudaGridDependencySynchronize();   // wait for prep's x-bar

    // ---- load x-bar bf16 tile (full K), persists across both tiles ----
    {
        const uint2* xh4 = (const uint2*)g_xh;
        #pragma unroll 4
        for (int i = t; i < NROWS * (DD / 4); i += 256) {
            int row  = i >> 6;
            int colq = i & 63;
            *(uint2*)(smem + SX + (uint32_t)(row * XSTR + colq * 4) * 2) = xh4[i];
        }
    }

    const int lane  = t & 31;
    const int w     = t >> 5;
    const int nbase = (w & 3) * 32;
    const int pcbas = (w >> 2) * 32;

    const int aRow = nbase + (lane & 7) + ((lane >> 3) & 1) * 8;
    const int aCol = (lane >> 4) * 8;
    const int bRow = pcbas + (lane & 7) + (lane >> 4) * 8;
    const int bCol = ((lane >> 3) & 1) * 8;

    const uint32_t aOffL = (uint32_t)(aRow * FB_STR + aCol) * 2;
    const uint32_t bB = sb + SX + (uint32_t)(bRow * XSTR + bCol) * 2;

    float* cs = (float*)(smem + CS_OFF);     // [4][64]
    float* cn = cs + 256;                    // [4][64]

    #pragma unroll 1
    for (int tile = 0; tile < 2; tile++) {
        const float4* f4 = fb + (size_t)(bid + tile * GRID_B) * TILE_N * 64;

        // ---- store chunk 0 (R holds it: prologue / prev-tile prefetch) ----
        #pragma unroll
        for (int j = 0; j < 8; j++) {
            int idx = t + 256 * j;
            int row = idx >> 4, q = idx & 15;
            *(uint2*)(smem + FB0 + (uint32_t)(row * FB_STR + q * 4) * 2) =
                make_uint2(cvt2(R[j].x, R[j].y), cvt2(R[j].z, R[j].w));
        }
        __syncthreads();

        float acc[2][4][4];
        #pragma unroll
        for (int i = 0; i < 2; i++)
            #pragma unroll
            for (int j = 0; j < 4; j++)
                #pragma unroll
                for (int q = 0; q < 4; q++) acc[i][j][q] = 0.0f;

        #pragma unroll
        for (int c = 0; c < 4; c++) {
            if (c < 3) {
                #pragma unroll
                for (int j = 0; j < 8; j++) {
                    int idx = t + 256 * j;
                    R[j] = f4[(idx >> 4) * 64 + (c + 1) * 16 + (idx & 15)];
                }
            } else if (tile == 0) {
                // prefetch next tile's chunk 0 during last MMA chunk
                const float4* f4n = fb + (size_t)(bid + GRID_B) * TILE_N * 64;
                #pragma unroll
                for (int j = 0; j < 8; j++) {
                    int idx = t + 256 * j;
                    R[j] = f4n[(idx >> 4) * 64 + (idx & 15)];
                }
            }
            const uint32_t aBuf = sb + ((c & 1) ? FB1 : FB0) + aOffL;
            #pragma unroll
            for (int kst = 0; kst < 4; kst++) {
                uint32_t af[2][4], bfr[2][4];
                ldsm4(af[0], aBuf + kst * 32);
                ldsm4(af[1], aBuf + kst * 32 + 16 * FB_STR * 2);
                ldsm4(bfr[0], bB + (c * KC + kst * 16) * 2);
                ldsm4(bfr[1], bB + (c * KC + kst * 16) * 2 + 16 * XSTR * 2);
                #pragma unroll
                for (int mt = 0; mt < 2; mt++)
                    #pragma unroll
                    for (int ntp = 0; ntp < 2; ntp++) {
                        mma16816(acc[mt][ntp * 2 + 0], af[mt], bfr[ntp][0], bfr[ntp][1]);
                        mma16816(acc[mt][ntp * 2 + 1], af[mt], bfr[ntp][2], bfr[ntp][3]);
                    }
            }
            if (c < 3) {
                const int dst = (c & 1) ? FB0 : FB1;
                #pragma unroll
                for (int j = 0; j < 8; j++) {
                    int idx = t + 256 * j;
                    int row = idx >> 4, q = idx & 15;
                    *(uint2*)(smem + dst + (uint32_t)(row * FB_STR + q * 4) * 2) =
                        make_uint2(cvt2(R[j].x, R[j].y), cvt2(R[j].z, R[j].w));
                }
                __syncthreads();
            }
        }

        // ---- all-register epilogue ----
        // Thread owns 8 pc-columns (nt in 0..3, parity h in 0..1), 4 rows each:
        // acc[mt][nt][h] (row r0+mt*16), acc[mt][nt][2+h] (row r0+8+mt*16).
        float s8[8], n8[8];
        #pragma unroll
        for (int nt = 0; nt < 4; nt++)
            #pragma unroll
            for (int h = 0; h < 2; h++) {
                float v0 = acc[0][nt][h]     * INV_TEMP;
                float v1 = acc[0][nt][2 + h] * INV_TEMP;
                float v2 = acc[1][nt][h]     * INV_TEMP;
                float v3 = acc[1][nt][2 + h] * INV_TEMP;
                s8[nt * 2 + h] = (__expf(v0) + __expf(v1)) + (__expf(v2) + __expf(v3));
                n8[nt * 2 + h] = fminf(fminf(v0, v1), fminf(v2, v3));
            }
        // reduce over the warp's 32 rows: lanes sharing (lane&3) hold the
        // remaining row groups -> xor-shfl over offsets 4, 8, 16.
        #pragma unroll
        for (int off = 4; off <= 16; off <<= 1)
            #pragma unroll
            for (int i = 0; i < 8; i++) {
                s8[i] += __shfl_xor_sync(0xFFFFFFFFu, s8[i], off);
                n8[i]  = fminf(n8[i], __shfl_xor_sync(0xFFFFFFFFu, n8[i], off));
            }
        __syncthreads();   // all warps done with FB1 reads (c=3) before cs/cn write
        if (lane < 4) {
            const int c0 = lane * 2;
            #pragma unroll
            for (int nt = 0; nt < 4; nt++)
                #pragma unroll
                for (int h = 0; h < 2; h++) {
                    const int col = pcbas + nt * 8 + c0 + h;
                    cs[(w & 3) * 64 + col] = s8[nt * 2 + h];
                    cn[(w & 3) * 64 + col] = n8[nt * 2 + h];
                }
        }
        __syncthreads();

        if (t < 64) {
            float s = 0.0f, mn = CUDART_INF_F;
            #pragma unroll
            for (int g = 0; g < 4; g++) {
                s += cs[g * 64 + t];
                mn = fminf(mn, cn[g * 64 + t]);
            }
            g_part[t * NB + (bid + tile * GRID_B)] = make_float2(s, mn);
        }
        // next tile's chunk-0 STS targets FB0 only (disjoint from cs/cn);
        // cs/cn reads complete before tile-1's chunk-1 STS (two barriers away).
    }
}

// ---------------------------------------------------------------------------
// Kernel C: per-row combine of the 512 packed partials + own-dot; LAST block
// also assembles the scalar loss. grid=64, block=128. PDL-dependent on gemm.
// ---------------------------------------------------------------------------
__global__ void combine_kernel(const float* __restrict__ features,
                               float* __restrict__ out) {
    const int row = blockIdx.x;
    const int t = threadIdx.x;       // 128
    const int w = t >> 5, l = t & 31;
    __shared__ float ps[4], pn[4], pd[4];
    __shared__ int isLast;

    // own-dot partial first: depends only on prep outputs (long complete)
    const int p = row >> 2;
    float d = g_xb[row * DD + t] * features[(size_t)p * DD + t]
            + g_xb[row * DD + t + 128] * features[(size_t)p * DD + t + 128];
    #pragma unroll
    for (int off = 16; off; off >>= 1)
        d += __shfl_xor_sync(0xFFFFFFFFu, d, off);

    // wait for gemm before touching its partials
    cudaGridDependencySynchronize();

    float s = 0.0f, mn = CUDART_INF_F;
    #pragma unroll
    for (int j = 0; j < 4; j++) {
        float2 pv = g_part[row * NB + t + 128 * j];
        s += pv.x;
        mn = fminf(mn, pv.y);
    }
    #pragma unroll
    for (int off = 16; off; off >>= 1) {
        s  += __shfl_xor_sync(0xFFFFFFFFu, s,  off);
        mn  = fminf(mn, __shfl_xor_sync(0xFFFFFFFFu, mn, off));
    }

    if (l == 0) { ps[w] = s; pn[w] = mn; pd[w] = d; }
    __syncthreads();

    if (t == 0) {
        float S = ps[0], MN = pn[0], D = pd[0];
        #pragma unroll
        for (int i = 1; i < 4; i++) {
            S += ps[i];
            MN = fminf(MN, pn[i]);
            D += pd[i];
        }
        g_rS[row] = S; g_rMin[row] = MN;
        g_own[row] = D * INV_TEMP;
        __threadfence();
        unsigned r = atomicAdd(&g_cnt, 1u);
        if (r == NROWS - 1) __threadfence();   // acquire all rows' results
        isLast = (r == NROWS - 1);
    }
    __syncthreads();

    if (isLast && t < 32) {
        float loss = 0.0f;
        if (t < PP) {
            const int p2 = t;
            float S = 0.0f;
            #pragma unroll
            for (int c = 0; c < CC; c++) S += g_rS[p2 * CC + c];
            #pragma unroll
            for (int c = 0; c < CC; c++) S -= expf(g_rMin[p2 * CC + c]);
            float pos = CUDART_INF_F;
            #pragma unroll
            for (int c = 0; c < CC; c++) pos = fminf(pos, g_own[p2 * CC + c]);
            S += expf(pos);
            loss = logf(S) - pos;
        }
        #pragma unroll
        for (int off = 16; off; off >>= 1)
            loss += __shfl_xor_sync(0xFFFFFFFFu, loss, off);
        if (t == 0) out[0] = loss * (1.0f / (float)PP);
    }
}

// ---------------------------------------------------------------------------
extern "C" void kernel_launch(void* const* d_in, const int* in_sizes, int n_in,
                              void* d_out, int out_size) {
    const float* inputs   = (const float*)d_in[0];   // [512, 256] f32
    const float* features = (const float*)d_in[4];   // [65536, 256] f32
    float* out = (float*)d_out;

    cudaFuncSetAttribute(gemm_reduce_kernel,
                         cudaFuncAttributeMaxDynamicSharedMemorySize, SMEM_BYTES);

    prep_kernel<<<NROWS, 512>>>(inputs);

    // gemm: PDL-dependent on prep
    {
        cudaLaunchAttribute attr[1];
        attr[0].id = cudaLaunchAttributeProgrammaticStreamSerialization;
        attr[0].val.programmaticStreamSerializationAllowed = 1;
        cudaLaunchConfig_t cfg = {};
        cfg.gridDim = dim3(GRID_B, 1, 1);
        cfg.blockDim = dim3(256, 1, 1);
        cfg.dynamicSmemBytes = SMEM_BYTES;
        cfg.stream = 0;
        cfg.attrs = attr;
        cfg.numAttrs = 1;
        cudaLaunchKernelEx(&cfg, gemm_reduce_kernel, features);
    }

    // combine: PDL-dependent on gemm
    {
        cudaLaunchAttribute attr[1];
        attr[0].id = cudaLaunchAttributeProgrammaticStreamSerialization;
        attr[0].val.programmaticStreamSerializationAllowed = 1;
        cudaLaunchConfig_t cfg = {};
        cfg.gridDim = dim3(NROWS, 1, 1);
        cfg.blockDim = dim3(128, 1, 1);
        cfg.dynamicSmemBytes = 0;
        cfg.stream = 0;
        cfg.attrs = attr;
        cfg.numAttrs = 1;
        cudaLaunchKernelEx(&cfg, combine_kernel, features, out);
    }
}